// round 1
// baseline (speedup 1.0000x reference)
#include <cuda_runtime.h>
#include <cuda_bf16.h>

// Problem constants: x is (8, 4096, 512) fp32, kappa scalar fp32.
// Output: grad (512*512) ++ correlation_loss ++ whitening_loss  (262146 fp32)
#define D     512
#define NTOT  32768          // 8*4096 samples
#define TILE  128
#define KB    16
#define SPLITK 59            // 10 tiles * 59 = 590 CTAs ~ 2 waves @ 2 CTAs/SM

// -------- scratch (device globals; no allocation) --------
__device__ float  g_gram[D * D];   // accumulated X^T X (upper-triangle tiles valid)
__device__ double g_corr;          // sum_n (s2^2 - s4)
__device__ double g_whit;          // sum_n (s4 - 2*s2 + d)

// upper-triangle 128x128 tile list (4x4 tile grid, ti <= tj)
__constant__ int c_ti[10] = {0,0,0,0,1,1,1,2,2,3};
__constant__ int c_tj[10] = {0,1,2,3,1,2,3,2,3,3};

// -------- kernel 0: zero scratch (graph replays re-run this) --------
__global__ void init_kernel() {
    int idx = blockIdx.x * blockDim.x + threadIdx.x;
    if (idx < D * D) g_gram[idx] = 0.0f;
    if (idx == 0) { g_corr = 0.0; g_whit = 0.0; }
}

// -------- kernel 1: per-sample s2/s4 -> loss sums --------
// One warp per sample row (512 floats). 256 threads = 8 rows per block.
__global__ void loss_kernel(const float* __restrict__ x) {
    int row  = blockIdx.x * (blockDim.x >> 5) + (threadIdx.x >> 5);
    int lane = threadIdx.x & 31;
    const float* xr = x + (size_t)row * D;

    float s2 = 0.0f, s4 = 0.0f;
#pragma unroll
    for (int u = 0; u < D / 32; ++u) {
        float v  = xr[lane + 32 * u];
        float v2 = v * v;
        s2 += v2;
        s4 += v2 * v2;
    }
#pragma unroll
    for (int o = 16; o > 0; o >>= 1) {
        s2 += __shfl_xor_sync(0xFFFFFFFFu, s2, o);
        s4 += __shfl_xor_sync(0xFFFFFFFFu, s4, o);
    }

    __shared__ double blk_c, blk_w;
    if (threadIdx.x == 0) { blk_c = 0.0; blk_w = 0.0; }
    __syncthreads();
    if (lane == 0) {
        double ds2 = (double)s2, ds4 = (double)s4;
        atomicAdd(&blk_c, ds2 * ds2 - ds4);
        atomicAdd(&blk_w, ds4 - 2.0 * ds2 + (double)D);
    }
    __syncthreads();
    if (threadIdx.x == 0) {
        atomicAdd(&g_corr, blk_c);
        atomicAdd(&g_whit, blk_w);
    }
}

// -------- kernel 2: gram = X^T X  (SYRK, upper-triangle tiles, split-K) --------
// blockIdx.x: tile id (0..9), blockIdx.y: split-K chunk.
// 256 threads, each computes an 8x8 fp32 micro-tile of a 128x128 tile.
__global__ void __launch_bounds__(256, 2) gram_kernel(const float* __restrict__ x) {
    __shared__ float As[KB][TILE];
    __shared__ float Bs[KB][TILE];

    const int ti = c_ti[blockIdx.x];
    const int tj = c_tj[blockIdx.x];
    const int iBase = ti * TILE;
    const int jBase = tj * TILE;

    const int chunk = (NTOT + gridDim.y - 1) / gridDim.y;
    const int k0 = blockIdx.y * chunk;
    const int k1 = min(k0 + chunk, NTOT);
    if (k0 >= k1) return;

    const int t  = threadIdx.x;
    const int r  = t >> 4;          // 0..15 -> output rows r*8..r*8+7
    const int cc = t & 15;          // 0..15 -> output cols cc*8..cc*8+7

    // load mapping: thread t fills As/Bs row kk = t/16, cols (t%16)*8 .. +7
    const int lkk  = t >> 4;
    const int lcol = (t & 15) * 8;

    float acc[8][8];
#pragma unroll
    for (int u = 0; u < 8; ++u)
#pragma unroll
        for (int v = 0; v < 8; ++v) acc[u][v] = 0.0f;

    const float4 z4 = make_float4(0.f, 0.f, 0.f, 0.f);

    for (int ks = k0; ks < k1; ks += KB) {
        // stage global loads in registers (overlaps previous compute)
        int k = ks + lkk;
        float4 a0, a1, b0, b1;
        if (k < k1) {
            const float* rowp = x + (size_t)k * D;
            a0 = *(const float4*)(rowp + iBase + lcol);
            a1 = *(const float4*)(rowp + iBase + lcol + 4);
            b0 = *(const float4*)(rowp + jBase + lcol);
            b1 = *(const float4*)(rowp + jBase + lcol + 4);
        } else {
            a0 = a1 = b0 = b1 = z4;
        }
        __syncthreads();   // previous compute done before overwrite
        *(float4*)&As[lkk][lcol]     = a0;
        *(float4*)&As[lkk][lcol + 4] = a1;
        *(float4*)&Bs[lkk][lcol]     = b0;
        *(float4*)&Bs[lkk][lcol + 4] = b1;
        __syncthreads();

#pragma unroll
        for (int kk = 0; kk < KB; ++kk) {
            float4 av0 = *(const float4*)&As[kk][r * 8];
            float4 av1 = *(const float4*)&As[kk][r * 8 + 4];
            float4 bv0 = *(const float4*)&Bs[kk][cc * 8];
            float4 bv1 = *(const float4*)&Bs[kk][cc * 8 + 4];
            float a[8] = {av0.x, av0.y, av0.z, av0.w, av1.x, av1.y, av1.z, av1.w};
            float b[8] = {bv0.x, bv0.y, bv0.z, bv0.w, bv1.x, bv1.y, bv1.z, bv1.w};
#pragma unroll
            for (int u = 0; u < 8; ++u)
#pragma unroll
                for (int v = 0; v < 8; ++v)
                    acc[u][v] = fmaf(a[u], b[v], acc[u][v]);
        }
    }

    // split-K accumulate into scratch
#pragma unroll
    for (int u = 0; u < 8; ++u) {
        int gi = iBase + r * 8 + u;
#pragma unroll
        for (int v = 0; v < 8; ++v) {
            int gj = jBase + cc * 8 + v;
            atomicAdd(&g_gram[gi * D + gj], acc[u][v]);
        }
    }
}

// -------- kernel 3: finalize grad + emit scalars --------
__global__ void finalize_kernel(const float* __restrict__ kappa_p,
                                float* __restrict__ out) {
    int idx = blockIdx.x * blockDim.x + threadIdx.x;
    const float kappa = *kappa_p;
    const float invN  = 1.0f / (float)NTOT;
    if (idx < D * D) {
        int i = idx >> 9;          // D = 512
        int j = idx & (D - 1);
        int ti = i >> 7, tj = j >> 7;
        float g = (ti <= tj) ? g_gram[idx] : g_gram[j * D + i];
        float m = g * invN;
        out[idx] = (i == j) ? kappa * (m - 1.0f) : (1.0f - kappa) * m;
    }
    if (idx == 0) {
        double scale = 1.0 / ((double)NTOT * (double)D * (double)D);
        out[D * D]     = (float)(g_corr * scale);
        out[D * D + 1] = (float)(g_whit * scale);
    }
}

extern "C" void kernel_launch(void* const* d_in, const int* in_sizes, int n_in,
                              void* d_out, int out_size) {
    const float* x     = (const float*)d_in[0];
    const float* kappa = (const float*)d_in[1];
    float*       out   = (float*)d_out;

    init_kernel<<<(D * D + 255) / 256, 256>>>();
    loss_kernel<<<NTOT / 8, 256>>>(x);
    dim3 grid(10, SPLITK);
    gram_kernel<<<grid, 256>>>(x);
    finalize_kernel<<<(D * D + 255) / 256, 256>>>(kappa, out);
}

// round 3
// speedup vs baseline: 2.1343x; 2.1343x over previous
#include <cuda_runtime.h>
#include <cuda_bf16.h>
#include <cstdint>

// ---------------- problem constants ----------------
#define D      512
#define NTOT   32768            // 8*4096 samples
#define MT     128              // CTA gemm M tile
#define NT     64               // CTA gemm N tile
#define KC     64               // k per smem stage (64 bf16 = 128B rows)
#define NSPLIT 8
#define KSPLIT (NTOT / NSPLIT)  // 4096
#define NCHUNK (KSPLIT / KC)    // 64

// ---------------- device scratch (no allocation) ----------------
__device__ __nv_bfloat16 g_Ht[(size_t)D * NTOT];   // 32 MB, K-major transposed hi
__device__ __nv_bfloat16 g_Lt[(size_t)D * NTOT];   // 32 MB, K-major transposed lo
__device__ float  g_c[D * D];                      // C = HH + HL + HL^T
__device__ double g_corr, g_whit;

__device__ __forceinline__ uint32_t smem_to_u32(const void* p) {
    uint32_t a;
    asm("{ .reg .u64 t; cvta.to.shared.u64 t, %1; cvt.u32.u64 %0, t; }" : "=r"(a) : "l"(p));
    return a;
}

// ---------------- kernel 0: zero scratch ----------------
__global__ void init_kernel() {
    int idx = blockIdx.x * blockDim.x + threadIdx.x;
    if (idx < D * D) g_c[idx] = 0.0f;
    if (idx == 0) { g_corr = 0.0; g_whit = 0.0; }
}

// ---------------- kernel 1: transpose + hi/lo bf16 split ----------------
__global__ void __launch_bounds__(256) convert_kernel(const float* __restrict__ x) {
    __shared__ float tile[64][65];
    const int n0 = blockIdx.x * 64;
    const int d0 = blockIdx.y * 64;
    const int tid = threadIdx.x;
    const int r  = tid >> 4;
    const int c4 = (tid & 15) * 4;
#pragma unroll
    for (int p = 0; p < 4; ++p) {
        int n = p * 16 + r;
        float4 v = *reinterpret_cast<const float4*>(x + (size_t)(n0 + n) * D + d0 + c4);
        tile[n][c4 + 0] = v.x; tile[n][c4 + 1] = v.y;
        tile[n][c4 + 2] = v.z; tile[n][c4 + 3] = v.w;
    }
    __syncthreads();
    const int dd = tid >> 2;
    const int nb = (tid & 3) * 16;
    __align__(16) __nv_bfloat16 hi[16];
    __align__(16) __nv_bfloat16 lo[16];
#pragma unroll
    for (int u = 0; u < 16; ++u) {
        float v = tile[nb + u][dd];
        __nv_bfloat16 h = __float2bfloat16(v);
        hi[u] = h;
        lo[u] = __float2bfloat16(v - __bfloat162float(h));
    }
    size_t base = (size_t)(d0 + dd) * NTOT + (size_t)(n0 + nb);
    *reinterpret_cast<uint4*>(&g_Ht[base])     = *reinterpret_cast<uint4*>(hi);
    *reinterpret_cast<uint4*>(&g_Ht[base + 8]) = *reinterpret_cast<uint4*>(hi + 8);
    *reinterpret_cast<uint4*>(&g_Lt[base])     = *reinterpret_cast<uint4*>(lo);
    *reinterpret_cast<uint4*>(&g_Lt[base + 8]) = *reinterpret_cast<uint4*>(lo + 8);
}

// ---------------- kernel 2: per-sample s2/s4 losses ----------------
__global__ void loss_kernel(const float* __restrict__ x) {
    int row  = blockIdx.x * 8 + (threadIdx.x >> 5);
    int lane = threadIdx.x & 31;
    const float4* xr = reinterpret_cast<const float4*>(x + (size_t)row * D);
    float s2 = 0.0f, s4 = 0.0f;
#pragma unroll
    for (int u = 0; u < 4; ++u) {
        float4 v = xr[lane + 32 * u];
        float a = v.x * v.x, b = v.y * v.y, c = v.z * v.z, d = v.w * v.w;
        s2 += a + b + c + d;
        s4 += a * a + b * b + c * c + d * d;
    }
#pragma unroll
    for (int o = 16; o > 0; o >>= 1) {
        s2 += __shfl_xor_sync(0xFFFFFFFFu, s2, o);
        s4 += __shfl_xor_sync(0xFFFFFFFFu, s4, o);
    }
    __shared__ double blk_c, blk_w;
    if (threadIdx.x == 0) { blk_c = 0.0; blk_w = 0.0; }
    __syncthreads();
    if (lane == 0) {
        double ds2 = (double)s2, ds4 = (double)s4;
        atomicAdd(&blk_c, ds2 * ds2 - ds4);
        atomicAdd(&blk_w, ds4 - 2.0 * ds2 + (double)D);
    }
    __syncthreads();
    if (threadIdx.x == 0) {
        atomicAdd(&g_corr, blk_c);
        atomicAdd(&g_whit, blk_w);
    }
}

// ---------------- kernel 3: mma.sync gram ----------------
// Per CTA: C_tile(i,j) 128x64.  HH = H_i^T H_j, HL = H_i^T L_j  (fp32 accum)
// Epilogue: g_c[i][j] += HH + HL ;  g_c[j][i] += HL
//
// smem stage: A rows 0..127 (H, iBase), BH rows 0..63 (H, jBase), BL rows 0..63
// (L, jBase). Rows are 64 bf16 = 128B, SW128 swizzled.
#define STAGE_BYTES 32768
#define A_AREA  0
#define BH_AREA 16384
#define BL_AREA 24576
#define SMEM_BYTES (2 * STAGE_BYTES)

__device__ __forceinline__ uint32_t sw128(uint32_t off) {
    return off ^ ((off >> 3) & 0x70);
}
__device__ __forceinline__ void cp16(uint32_t saddr, const void* gaddr) {
    asm volatile("cp.async.cg.shared.global [%0], [%1], 16;" :: "r"(saddr), "l"(gaddr));
}
__device__ __forceinline__ void cp_commit() {
    asm volatile("cp.async.commit_group;" ::: "memory");
}
template <int N>
__device__ __forceinline__ void cp_wait() {
    asm volatile("cp.async.wait_group %0;" :: "n"(N) : "memory");
}
__device__ __forceinline__ void ldsm_x4(uint32_t* r, uint32_t addr) {
    asm volatile("ldmatrix.sync.aligned.m8n8.x4.shared.b16 {%0,%1,%2,%3}, [%4];"
                 : "=r"(r[0]), "=r"(r[1]), "=r"(r[2]), "=r"(r[3]) : "r"(addr));
}
__device__ __forceinline__ void mma_bf16(float* c, const uint32_t* a, const uint32_t* b) {
    asm volatile(
        "mma.sync.aligned.m16n8k16.row.col.f32.bf16.bf16.f32 "
        "{%0,%1,%2,%3}, {%4,%5,%6,%7}, {%8,%9}, {%0,%1,%2,%3};"
        : "+f"(c[0]), "+f"(c[1]), "+f"(c[2]), "+f"(c[3])
        : "r"(a[0]), "r"(a[1]), "r"(a[2]), "r"(a[3]), "r"(b[0]), "r"(b[1]));
}

__device__ __forceinline__ void load_stage_async(uint32_t smem_u, int stage,
                                                 int iBase, int jBase, int k0, int tid) {
    const uint32_t sbase = smem_u + stage * STAGE_BYTES;
#pragma unroll
    for (int it = 0; it < 8; ++it) {
        int idx = it * 256 + tid;       // 2048 x 16B units
        int row = idx >> 3;
        int sub = idx & 7;
        const __nv_bfloat16* src;
        uint32_t area;
        int lr;
        if (row < MT)           { lr = row;          src = g_Ht + (size_t)(iBase + lr) * NTOT; area = A_AREA; }
        else if (row < MT + NT) { lr = row - MT;     src = g_Ht + (size_t)(jBase + lr) * NTOT; area = BH_AREA; }
        else                    { lr = row - MT - NT; src = g_Lt + (size_t)(jBase + lr) * NTOT; area = BL_AREA; }
        uint32_t off = sw128((uint32_t)(lr * 128 + sub * 16));
        cp16(sbase + area + off, src + k0 + sub * 8);
    }
}

__global__ void __launch_bounds__(256) gram_mma_kernel() {
    extern __shared__ __align__(1024) char smem[];
    const uint32_t smem_u = smem_to_u32(smem);
    const int tid  = threadIdx.x;
    const int wid  = tid >> 5;
    const int lane = tid & 31;
    const int iBase = blockIdx.x * MT;
    const int jBase = blockIdx.y * NT;
    const int ksb   = blockIdx.z * KSPLIT;

    const int m0 = (wid & 3) * 32;   // warp tile row within CTA tile
    const int n0 = (wid >> 2) * 32;  // warp tile col within CTA tile

    // ldmatrix per-lane address components (pre-swizzle byte offsets)
    const uint32_t a_off0 = (uint32_t)((m0 + (lane & 15)) * 128 + (lane >> 4) * 16);
    const int bj   = ((lane & 16) >> 1) + (lane & 7);     // row-within-16 of B frag pair
    const uint32_t b_colb = (uint32_t)((lane & 8) * 2);   // 0 or 16
    const uint32_t b_off0 = (uint32_t)((n0 + bj) * 128) + b_colb;

    float accH[2][4][4];
    float accL[2][4][4];
#pragma unroll
    for (int mf = 0; mf < 2; ++mf)
#pragma unroll
        for (int nf = 0; nf < 4; ++nf)
#pragma unroll
            for (int e = 0; e < 4; ++e) { accH[mf][nf][e] = 0.f; accL[mf][nf][e] = 0.f; }

    load_stage_async(smem_u, 0, iBase, jBase, ksb, tid);
    cp_commit();

    for (int c = 0; c < NCHUNK; ++c) {
        if (c + 1 < NCHUNK) {
            load_stage_async(smem_u, (c + 1) & 1, iBase, jBase, ksb + (c + 1) * KC, tid);
            cp_commit();
            cp_wait<1>();
        } else {
            cp_wait<0>();
        }
        __syncthreads();

        const uint32_t sbase = smem_u + (c & 1) * STAGE_BYTES;
#pragma unroll
        for (int ks = 0; ks < KC / 16; ++ks) {
            const uint32_t kshift = (uint32_t)(ks * 32);
            uint32_t a[2][4], bh[2][4], bl[2][4];
#pragma unroll
            for (int mf = 0; mf < 2; ++mf)
                ldsm_x4(a[mf], sbase + A_AREA + sw128(a_off0 + (uint32_t)(mf * 2048) + kshift));
#pragma unroll
            for (int np = 0; np < 2; ++np) {
                uint32_t boff = b_off0 + (uint32_t)(np * 16 * 128) + kshift;
                ldsm_x4(bh[np], sbase + BH_AREA + sw128(boff));
                ldsm_x4(bl[np], sbase + BL_AREA + sw128(boff));
            }
#pragma unroll
            for (int mf = 0; mf < 2; ++mf)
#pragma unroll
                for (int np = 0; np < 2; ++np) {
                    mma_bf16(accH[mf][np * 2 + 0], a[mf], &bh[np][0]);
                    mma_bf16(accH[mf][np * 2 + 1], a[mf], &bh[np][2]);
                    mma_bf16(accL[mf][np * 2 + 0], a[mf], &bl[np][0]);
                    mma_bf16(accL[mf][np * 2 + 1], a[mf], &bl[np][2]);
                }
        }
        __syncthreads();
    }

    // epilogue: atomically accumulate.  c frag element map (m16n8):
    //   e0:(g, 2t) e1:(g, 2t+1) e2:(g+8, 2t) e3:(g+8, 2t+1)
    const int g = lane >> 2;
    const int t = lane & 3;
#pragma unroll
    for (int mf = 0; mf < 2; ++mf)
#pragma unroll
        for (int nf = 0; nf < 4; ++nf)
#pragma unroll
            for (int e = 0; e < 4; ++e) {
                int i = iBase + m0 + mf * 16 + g + (e >> 1) * 8;
                int j = jBase + n0 + nf * 8 + 2 * t + (e & 1);
                float hh = accH[mf][nf][e];
                float hl = accL[mf][nf][e];
                atomicAdd(&g_c[i * D + j], hh + hl);
                atomicAdd(&g_c[j * D + i], hl);
            }
}

// ---------------- kernel 4: finalize ----------------
__global__ void finalize_kernel(const float* __restrict__ kappa_p, float* __restrict__ out) {
    int idx = blockIdx.x * blockDim.x + threadIdx.x;
    const float kappa = *kappa_p;
    const float invN  = 1.0f / (float)NTOT;
    if (idx < D * D) {
        int i = idx >> 9;
        int j = idx & (D - 1);
        float m = g_c[idx] * invN;
        out[idx] = (i == j) ? kappa * (m - 1.0f) : (1.0f - kappa) * m;
    }
    if (idx == 0) {
        double scale = 1.0 / ((double)NTOT * (double)D * (double)D);
        out[D * D]     = (float)(g_corr * scale);
        out[D * D + 1] = (float)(g_whit * scale);
    }
}

extern "C" void kernel_launch(void* const* d_in, const int* in_sizes, int n_in,
                              void* d_out, int out_size) {
    const float* x     = (const float*)d_in[0];
    const float* kappa = (const float*)d_in[1];
    float*       out   = (float*)d_out;

    cudaFuncSetAttribute(gram_mma_kernel, cudaFuncAttributeMaxDynamicSharedMemorySize, SMEM_BYTES);

    init_kernel<<<(D * D + 255) / 256, 256>>>();
    convert_kernel<<<dim3(NTOT / 64, D / 64), 256>>>(x);
    loss_kernel<<<NTOT / 8, 256>>>(x);
    gram_mma_kernel<<<dim3(D / MT, D / NT, NSPLIT), 256, SMEM_BYTES>>>();
    finalize_kernel<<<(D * D + 255) / 256, 256>>>(kappa, out);
}